// round 1
// baseline (speedup 1.0000x reference)
#include <cuda_runtime.h>
#include <cstdint>

#define NUM_SEG 2048
#define EPS 1e-6f

__device__ unsigned int g_min[NUM_SEG];
__device__ unsigned int g_max[NUM_SEG];
__device__ float2       g_prm[NUM_SEG];   // (mn, 1/(mx-mn+eps))

// Monotonic float<->uint order mapping (total order incl. sign).
__device__ __forceinline__ unsigned int f2ord(float f) {
    unsigned int u = __float_as_uint(f);
    return (u & 0x80000000u) ? ~u : (u | 0x80000000u);
}
__device__ __forceinline__ float ord2f(unsigned int u) {
    u = (u & 0x80000000u) ? (u ^ 0x80000000u) : ~u;
    return __uint_as_float(u);
}

__global__ void mm_init() {
    int i = blockIdx.x * blockDim.x + threadIdx.x;
    if (i < NUM_SEG) { g_min[i] = 0xFFFFFFFFu; g_max[i] = 0u; }
}

// Pass 1: each warp handles 2 rows (half-warp per row, 1 float4 per lane).
// Warp's 32 LDG.128 lanes cover 512 contiguous bytes -> fully coalesced.
__global__ void mm_pass1(const float4* __restrict__ x4,
                         const int* __restrict__ seg, int nrows) {
    int gtid   = blockIdx.x * blockDim.x + threadIdx.x;
    int warpid = gtid >> 5;
    int lane   = threadIdx.x & 31;
    int half   = lane >> 4;      // which of the 2 rows
    int hl     = lane & 15;      // float4 index within row (row = 16 float4)
    int row    = warpid * 2 + half;

    unsigned int umin = 0xFFFFFFFFu;
    unsigned int umax = 0u;
    if (row < nrows) {
        float4 v = x4[row * 16 + hl];
        float mn = fminf(fminf(v.x, v.y), fminf(v.z, v.w));
        float mx = fmaxf(fmaxf(v.x, v.y), fmaxf(v.z, v.w));
        umin = f2ord(mn);
        umax = f2ord(mx);
    }
    // Reduce within each 16-lane half-warp.
    #pragma unroll
    for (int o = 8; o > 0; o >>= 1) {
        umin = min(umin, __shfl_down_sync(0xFFFFFFFFu, umin, o, 16));
        umax = max(umax, __shfl_down_sync(0xFFFFFFFFu, umax, o, 16));
    }
    if (hl == 0 && row < nrows) {
        int s = __ldg(&seg[row]);
        atomicMin(&g_min[s], umin);   // result unused -> RED (no return)
        atomicMax(&g_max[s], umax);
    }
}

// Prep: turn uint min/max into (mn, inv) so pass 2 is a single FMA per elem.
__global__ void mm_prep() {
    int i = blockIdx.x * blockDim.x + threadIdx.x;
    if (i < NUM_SEG) {
        float mn = ord2f(g_min[i]);
        float mx = ord2f(g_max[i]);
        float inv = 1.0f / (mx - mn + EPS);   // empty segs -> NaN, never read
        g_prm[i] = make_float2(mn, inv);
    }
}

// Pass 2: one float4 per thread. seg[row] shared by 16 consecutive threads
// (L1 broadcast); g_prm is 16 KB, L2-resident.
__global__ void mm_pass2(const float4* __restrict__ x4,
                         const int* __restrict__ seg,
                         float4* __restrict__ o4, int n4) {
    int i = blockIdx.x * blockDim.x + threadIdx.x;
    if (i >= n4) return;
    int row = i >> 4;                  // 16 float4 per 64-wide row
    int s = __ldg(&seg[row]);
    float2 p = g_prm[s];
    float4 v = x4[i];
    float4 r;
    r.x = (v.x - p.x) * p.y;
    r.y = (v.y - p.x) * p.y;
    r.z = (v.z - p.x) * p.y;
    r.w = (v.w - p.x) * p.y;
    o4[i] = r;
}

extern "C" void kernel_launch(void* const* d_in, const int* in_sizes, int n_in,
                              void* d_out, int out_size) {
    const float* x   = (const float*)d_in[0];
    const int*   seg = (const int*)d_in[1];
    float*       out = (float*)d_out;

    int nrows = in_sizes[1];          // 1,000,000
    int n4    = in_sizes[0] / 4;      // 16,000,000 float4

    mm_init<<<(NUM_SEG + 255) / 256, 256>>>();

    int nwarps  = (nrows + 1) / 2;                 // 2 rows per warp
    int blocks1 = (nwarps * 32 + 255) / 256;
    mm_pass1<<<blocks1, 256>>>((const float4*)x, seg, nrows);

    mm_prep<<<(NUM_SEG + 255) / 256, 256>>>();

    mm_pass2<<<(n4 + 255) / 256, 256>>>((const float4*)x, seg, (float4*)out, n4);
}

// round 2
// speedup vs baseline: 2.8515x; 2.8515x over previous
#include <cuda_runtime.h>
#include <cstdint>

#define NUM_SEG 2048
#define EPS 1e-6f

#define P1_ITERS 8
#define P1_ROWS  (16 * P1_ITERS)   // 128 rows per 256-thread block

__device__ unsigned int g_min[NUM_SEG];
__device__ unsigned int g_max[NUM_SEG];
__device__ float2       g_prm[NUM_SEG];   // (mn, 1/(mx-mn+eps))

// Monotonic float<->uint order mapping (total order incl. sign).
__device__ __forceinline__ unsigned int f2ord(float f) {
    unsigned int u = __float_as_uint(f);
    return (u & 0x80000000u) ? ~u : (u | 0x80000000u);
}
__device__ __forceinline__ float ord2f(unsigned int u) {
    u = (u & 0x80000000u) ? (u ^ 0x80000000u) : ~u;
    return __uint_as_float(u);
}

__global__ void mm_init() {
    int i = blockIdx.x * blockDim.x + threadIdx.x;
    if (i < NUM_SEG) { g_min[i] = 0xFFFFFFFFu; g_max[i] = 0u; }
}

// Pass 1: 256 threads, 128 contiguous rows per block (2 rows/warp/iter, 8 iters).
// Half-warp per row, one float4 per lane -> every LDG.128 fully coalesced and
// 8 independent loads per thread are front-batched (high MLP).
// seg is SORTED -> a block spans ~1-2 segments. Aggregate per-row results in
// smem, then issue ONE global RED per distinct segment per block. This removes
// the hot-address L2-atomic serialization that dominated R0.
__global__ void __launch_bounds__(256) mm_pass1(const float4* __restrict__ x4,
                                                const int* __restrict__ seg,
                                                int nrows) {
    __shared__ int          s_seg[P1_ROWS];
    __shared__ unsigned int s_min[P1_ROWS];
    __shared__ unsigned int s_max[P1_ROWS];

    const int base = blockIdx.x * P1_ROWS;
    const int w    = threadIdx.x >> 5;
    const int lane = threadIdx.x & 31;
    const int half = lane >> 4;      // which of the warp's 2 rows this iter
    const int hl   = lane & 15;      // float4 index within the 64-wide row

    #pragma unroll
    for (int it = 0; it < P1_ITERS; ++it) {
        const int local = it * 16 + w * 2 + half;
        const int row   = base + local;

        unsigned int umin = 0xFFFFFFFFu;
        unsigned int umax = 0u;
        if (row < nrows) {
            float4 v = __ldcs(&x4[row * 16 + hl]);
            float mn = fminf(fminf(v.x, v.y), fminf(v.z, v.w));
            float mx = fmaxf(fmaxf(v.x, v.y), fmaxf(v.z, v.w));
            umin = f2ord(mn);
            umax = f2ord(mx);
        }
        // Reduce within each 16-lane half-warp.
        #pragma unroll
        for (int o = 8; o > 0; o >>= 1) {
            umin = min(umin, __shfl_down_sync(0xFFFFFFFFu, umin, o, 16));
            umax = max(umax, __shfl_down_sync(0xFFFFFFFFu, umax, o, 16));
        }
        if (hl == 0) {
            int s = (row < nrows) ? __ldg(&seg[row]) : -1;
            s_seg[local] = s;
            s_min[local] = umin;
            s_max[local] = umax;
        }
    }
    __syncthreads();

    // Flush: first row of each distinct segment within the block scans its
    // run (sorted -> contiguous) and issues a single RED pair.
    const int t = threadIdx.x;
    if (t < P1_ROWS) {
        const int s = s_seg[t];
        if (s >= 0 && (t == 0 || s != s_seg[t - 1])) {
            unsigned int m = s_min[t];
            unsigned int M = s_max[t];
            for (int j = t + 1; j < P1_ROWS && s_seg[j] == s; ++j) {
                m = min(m, s_min[j]);
                M = max(M, s_max[j]);
            }
            atomicMin(&g_min[s], m);   // unused result -> RED
            atomicMax(&g_max[s], M);
        }
    }
}

// Prep: (mn, 1/(mx-mn+eps)) so pass 2 is a subtract + multiply per element.
__global__ void mm_prep() {
    int i = blockIdx.x * blockDim.x + threadIdx.x;
    if (i < NUM_SEG) {
        float mn = ord2f(g_min[i]);
        float mx = ord2f(g_max[i]);
        float inv = 1.0f / (mx - mn + EPS);   // empty segs -> garbage, never read
        g_prm[i] = make_float2(mn, inv);
    }
}

// Pass 2: 2 block-strided float4 per thread (both LDG.128 fully coalesced,
// MLP=2). Streaming loads/stores: data is touch-once, keep it out of L2's
// way. g_prm (16 KB) stays cached; seg hits L1 broadcast (16 threads/row).
__global__ void __launch_bounds__(256) mm_pass2(const float4* __restrict__ x4,
                                                const int* __restrict__ seg,
                                                float4* __restrict__ o4, int n4) {
    const int i0 = blockIdx.x * (blockDim.x * 2) + threadIdx.x;
    const int i1 = i0 + blockDim.x;

    if (i1 < n4) {
        float4 v0 = __ldcs(&x4[i0]);
        float4 v1 = __ldcs(&x4[i1]);
        int   s0 = __ldg(&seg[i0 >> 4]);
        int   s1 = __ldg(&seg[i1 >> 4]);
        float2 p0 = g_prm[s0];
        float2 p1 = g_prm[s1];
        float4 r0, r1;
        r0.x = (v0.x - p0.x) * p0.y;  r0.y = (v0.y - p0.x) * p0.y;
        r0.z = (v0.z - p0.x) * p0.y;  r0.w = (v0.w - p0.x) * p0.y;
        r1.x = (v1.x - p1.x) * p1.y;  r1.y = (v1.y - p1.x) * p1.y;
        r1.z = (v1.z - p1.x) * p1.y;  r1.w = (v1.w - p1.x) * p1.y;
        __stcs(&o4[i0], r0);
        __stcs(&o4[i1], r1);
    } else {
        // Tail (only the last block can land here).
        for (int i = i0; i < n4; i += blockDim.x) {
            if (i >= n4) break;
            float4 v = __ldcs(&x4[i]);
            int s = __ldg(&seg[i >> 4]);
            float2 p = g_prm[s];
            float4 r;
            r.x = (v.x - p.x) * p.y;  r.y = (v.y - p.x) * p.y;
            r.z = (v.z - p.x) * p.y;  r.w = (v.w - p.x) * p.y;
            __stcs(&o4[i], r);
        }
    }
}

extern "C" void kernel_launch(void* const* d_in, const int* in_sizes, int n_in,
                              void* d_out, int out_size) {
    const float* x   = (const float*)d_in[0];
    const int*   seg = (const int*)d_in[1];
    float*       out = (float*)d_out;

    int nrows = in_sizes[1];          // 1,000,000
    int n4    = in_sizes[0] / 4;      // 16,000,000 float4

    mm_init<<<(NUM_SEG + 255) / 256, 256>>>();

    int blocks1 = (nrows + P1_ROWS - 1) / P1_ROWS;
    mm_pass1<<<blocks1, 256>>>((const float4*)x, seg, nrows);

    mm_prep<<<(NUM_SEG + 255) / 256, 256>>>();

    int blocks2 = (n4 + 511) / 512;   // 2 float4 per thread
    mm_pass2<<<blocks2, 256>>>((const float4*)x, seg, (float4*)out, n4);
}

// round 3
// speedup vs baseline: 3.3300x; 1.1678x over previous
#include <cuda_runtime.h>
#include <cstdint>

#define NUM_SEG 2048
#define EPS 1e-6f

#define P1_ROWS  256                  // rows per block in pass 1
#define P1_SLOTS 64                   // smem segment slots (slow path)

__device__ unsigned int g_min[NUM_SEG];
__device__ unsigned int g_max[NUM_SEG];
__device__ float2       g_prm[NUM_SEG];   // (mn, 1/(mx-mn+eps))

// Monotonic float<->uint order mapping (total order incl. sign).
__device__ __forceinline__ unsigned int f2ord(float f) {
    unsigned int u = __float_as_uint(f);
    return (u & 0x80000000u) ? ~u : (u | 0x80000000u);
}
__device__ __forceinline__ float ord2f(unsigned int u) {
    u = (u & 0x80000000u) ? (u ^ 0x80000000u) : ~u;
    return __uint_as_float(u);
}
__device__ __forceinline__ void acc_f4(float4 v, unsigned int& umin, unsigned int& umax) {
    float mn = fminf(fminf(v.x, v.y), fminf(v.z, v.w));
    float mx = fmaxf(fmaxf(v.x, v.y), fmaxf(v.z, v.w));
    umin = min(umin, f2ord(mn));
    umax = max(umax, f2ord(mx));
}

// Pass 1: block covers 256 contiguous rows (4096 float4). seg is SORTED, so
// ~half the blocks lie entirely inside one segment -> fast path: pure
// register accumulation over 16 coalesced float4s per thread, one block
// reduce, 2 REDs. Boundary blocks: run-accumulate per thread (seg is
// nondecreasing along each thread's strided walk), flush runs into smem
// slot atomics, then <=P1_SLOTS REDs.
__global__ void __launch_bounds__(256) mm_pass1(const float4* __restrict__ x4,
                                                const int* __restrict__ seg,
                                                int nrows) {
    const int t        = threadIdx.x;
    const int lane     = t & 31;
    const int w        = t >> 5;
    const int base_row = blockIdx.x * P1_ROWS;
    const int base4    = base_row * 16;
    const int last_row = min(base_row + P1_ROWS - 1, nrows - 1);

    const int s0 = __ldg(&seg[base_row]);
    const int sL = __ldg(&seg[last_row]);

    if (s0 == sL && base_row + P1_ROWS <= nrows) {
        // ---- fast path: whole block is one segment ----
        unsigned int umin = 0xFFFFFFFFu, umax = 0u;
        #pragma unroll
        for (int k = 0; k < 16; ++k) {
            float4 v = __ldcs(&x4[base4 + k * 256 + t]);
            acc_f4(v, umin, umax);
        }
        // 32-lane reduce
        #pragma unroll
        for (int o = 16; o > 0; o >>= 1) {
            umin = min(umin, __shfl_down_sync(0xFFFFFFFFu, umin, o));
            umax = max(umax, __shfl_down_sync(0xFFFFFFFFu, umax, o));
        }
        __shared__ unsigned int wmin[8], wmax[8];
        if (lane == 0) { wmin[w] = umin; wmax[w] = umax; }
        __syncthreads();
        if (w == 0) {
            umin = (lane < 8) ? wmin[lane] : 0xFFFFFFFFu;
            umax = (lane < 8) ? wmax[lane] : 0u;
            #pragma unroll
            for (int o = 4; o > 0; o >>= 1) {
                umin = min(umin, __shfl_down_sync(0xFFFFFFFFu, umin, o));
                umax = max(umax, __shfl_down_sync(0xFFFFFFFFu, umax, o));
            }
            if (lane == 0) {
                atomicMin(&g_min[s0], umin);
                atomicMax(&g_max[s0], umax);
            }
        }
        return;
    }

    // ---- slow path: block contains >=1 segment boundary (or grid tail) ----
    __shared__ unsigned int sl_min[P1_SLOTS], sl_max[P1_SLOTS];
    if (t < P1_SLOTS) { sl_min[t] = 0xFFFFFFFFu; sl_max[t] = 0u; }
    __syncthreads();

    int cur_s = -1;
    unsigned int cmin = 0xFFFFFFFFu, cmax = 0u;
    #pragma unroll
    for (int k = 0; k < 16; ++k) {
        const int idx = base4 + k * 256 + t;
        const int row = idx >> 4;
        if (row < nrows) {
            const int s = __ldg(&seg[row]);
            if (s != cur_s) {
                if (cur_s >= 0) {
                    const int slot = cur_s - s0;
                    if (slot < P1_SLOTS) {
                        atomicMin(&sl_min[slot], cmin);
                        atomicMax(&sl_max[slot], cmax);
                    } else {
                        atomicMin(&g_min[cur_s], cmin);
                        atomicMax(&g_max[cur_s], cmax);
                    }
                }
                cur_s = s; cmin = 0xFFFFFFFFu; cmax = 0u;
            }
            float4 v = __ldcs(&x4[idx]);
            acc_f4(v, cmin, cmax);
        }
    }
    if (cur_s >= 0) {
        const int slot = cur_s - s0;
        if (slot < P1_SLOTS) {
            atomicMin(&sl_min[slot], cmin);
            atomicMax(&sl_max[slot], cmax);
        } else {
            atomicMin(&g_min[cur_s], cmin);
            atomicMax(&g_max[cur_s], cmax);
        }
    }
    __syncthreads();
    if (t < P1_SLOTS) {
        if (sl_min[t] != 0xFFFFFFFFu) atomicMin(&g_min[s0 + t], sl_min[t]);
        if (sl_max[t] != 0u)          atomicMax(&g_max[s0 + t], sl_max[t]);
    }
}

// Prep: (mn, 1/(mx-mn+eps)) so pass 2 is a subtract + multiply per element.
__global__ void mm_prep() {
    int i = blockIdx.x * blockDim.x + threadIdx.x;
    if (i < NUM_SEG) {
        float mn = ord2f(g_min[i]);
        float mx = ord2f(g_max[i]);
        float inv = 1.0f / (mx - mn + EPS);   // empty segs -> garbage, never read
        g_prm[i] = make_float2(mn, inv);
    }
}

// Pass 2: 4 block-strided float4 per thread, loads front-batched (MLP=4),
// streaming ld/st (touch-once data). g_prm (16 KB) L2-resident; seg hits
// L1 broadcast (16 consecutive threads share one row).
__global__ void __launch_bounds__(256) mm_pass2(const float4* __restrict__ x4,
                                                const int* __restrict__ seg,
                                                float4* __restrict__ o4, int n4) {
    const int stride = blockDim.x;
    const int i0 = blockIdx.x * (stride * 4) + threadIdx.x;

    if (i0 + 3 * stride < n4) {
        float4 v0 = __ldcs(&x4[i0]);
        float4 v1 = __ldcs(&x4[i0 + stride]);
        float4 v2 = __ldcs(&x4[i0 + 2 * stride]);
        float4 v3 = __ldcs(&x4[i0 + 3 * stride]);
        int s0 = __ldg(&seg[i0 >> 4]);
        int s1 = __ldg(&seg[(i0 + stride) >> 4]);
        int s2 = __ldg(&seg[(i0 + 2 * stride) >> 4]);
        int s3 = __ldg(&seg[(i0 + 3 * stride) >> 4]);
        float2 p0 = g_prm[s0], p1 = g_prm[s1], p2 = g_prm[s2], p3 = g_prm[s3];
        float4 r0, r1, r2, r3;
        r0.x=(v0.x-p0.x)*p0.y; r0.y=(v0.y-p0.x)*p0.y; r0.z=(v0.z-p0.x)*p0.y; r0.w=(v0.w-p0.x)*p0.y;
        r1.x=(v1.x-p1.x)*p1.y; r1.y=(v1.y-p1.x)*p1.y; r1.z=(v1.z-p1.x)*p1.y; r1.w=(v1.w-p1.x)*p1.y;
        r2.x=(v2.x-p2.x)*p2.y; r2.y=(v2.y-p2.x)*p2.y; r2.z=(v2.z-p2.x)*p2.y; r2.w=(v2.w-p2.x)*p2.y;
        r3.x=(v3.x-p3.x)*p3.y; r3.y=(v3.y-p3.x)*p3.y; r3.z=(v3.z-p3.x)*p3.y; r3.w=(v3.w-p3.x)*p3.y;
        __stcs(&o4[i0],              r0);
        __stcs(&o4[i0 + stride],     r1);
        __stcs(&o4[i0 + 2 * stride], r2);
        __stcs(&o4[i0 + 3 * stride], r3);
    } else {
        for (int i = i0; i < n4; i += stride) {
            float4 v = __ldcs(&x4[i]);
            int s = __ldg(&seg[i >> 4]);
            float2 p = g_prm[s];
            float4 r;
            r.x=(v.x-p.x)*p.y; r.y=(v.y-p.x)*p.y; r.z=(v.z-p.x)*p.y; r.w=(v.w-p.x)*p.y;
            __stcs(&o4[i], r);
        }
    }
}

extern "C" void kernel_launch(void* const* d_in, const int* in_sizes, int n_in,
                              void* d_out, int out_size) {
    const float* x   = (const float*)d_in[0];
    const int*   seg = (const int*)d_in[1];
    float*       out = (float*)d_out;

    int nrows = in_sizes[1];          // 1,000,000
    int n4    = in_sizes[0] / 4;      // 16,000,000 float4

    // init g_min=UINT_MAX / g_max=0 via byte-fill memsets (graph-capturable)
    void* pmin = nullptr; void* pmax = nullptr;
    cudaGetSymbolAddress(&pmin, g_min);
    cudaGetSymbolAddress(&pmax, g_max);
    cudaMemsetAsync(pmin, 0xFF, NUM_SEG * sizeof(unsigned int), 0);
    cudaMemsetAsync(pmax, 0x00, NUM_SEG * sizeof(unsigned int), 0);

    int blocks1 = (nrows + P1_ROWS - 1) / P1_ROWS;
    mm_pass1<<<blocks1, 256>>>((const float4*)x, seg, nrows);

    mm_prep<<<(NUM_SEG + 255) / 256, 256>>>();

    int blocks2 = (n4 + 1023) / 1024;   // 4 float4 per thread
    mm_pass2<<<blocks2, 256>>>((const float4*)x, seg, (float4*)out, n4);
}

// round 4
// speedup vs baseline: 3.4940x; 1.0492x over previous
#include <cuda_runtime.h>
#include <cstdint>

#define NUM_SEG 2048
#define EPS 1e-6f

#define P1_ROWS  64                   // rows per block in pass 1 (1024 float4)
#define P1_SLOTS 64                   // smem segment slots (slow path)

__device__ unsigned int g_min[NUM_SEG];
__device__ unsigned int g_max[NUM_SEG];
__device__ float2       g_prm[NUM_SEG];   // (mn, 1/(mx-mn+eps))

// Monotonic float<->uint order mapping (total order incl. sign).
__device__ __forceinline__ unsigned int f2ord(float f) {
    unsigned int u = __float_as_uint(f);
    return (u & 0x80000000u) ? ~u : (u | 0x80000000u);
}
__device__ __forceinline__ float ord2f(unsigned int u) {
    u = (u & 0x80000000u) ? (u ^ 0x80000000u) : ~u;
    return __uint_as_float(u);
}
__device__ __forceinline__ float f4min(float4 v) {
    return fminf(fminf(v.x, v.y), fminf(v.z, v.w));
}
__device__ __forceinline__ float f4max(float4 v) {
    return fmaxf(fmaxf(v.x, v.y), fmaxf(v.z, v.w));
}

// Pass 1: block covers 64 contiguous rows (1024 float4), 256 threads, 4
// block-strided float4 per thread, loads front-batched (MLP=4, same shape
// as pass2 which sustains ~7 TB/s). seg is SORTED: ~87% of 64-row blocks
// lie inside one segment -> fast path accumulates pure float min/max (no
// uint conversion in the loop), one block reduce in float, f2ord only at
// the 2 global REDs. Boundary blocks take a short run-accumulate slow path.
__global__ void __launch_bounds__(256) mm_pass1(const float4* __restrict__ x4,
                                                const int* __restrict__ seg,
                                                int nrows) {
    const int t        = threadIdx.x;
    const int lane     = t & 31;
    const int w        = t >> 5;
    const int base_row = blockIdx.x * P1_ROWS;
    const int base4    = base_row * 16;
    const int last_row = min(base_row + P1_ROWS - 1, nrows - 1);

    const int s0 = __ldg(&seg[base_row]);
    const int sL = __ldg(&seg[last_row]);

    if (s0 == sL && base_row + P1_ROWS <= nrows) {
        // ---- fast path: whole block is one segment ----
        float4 v0 = __ldcs(&x4[base4 + t]);
        float4 v1 = __ldcs(&x4[base4 + 256 + t]);
        float4 v2 = __ldcs(&x4[base4 + 512 + t]);
        float4 v3 = __ldcs(&x4[base4 + 768 + t]);
        float mn = fminf(fminf(f4min(v0), f4min(v1)), fminf(f4min(v2), f4min(v3)));
        float mx = fmaxf(fmaxf(f4max(v0), f4max(v1)), fmaxf(f4max(v2), f4max(v3)));
        // 32-lane reduce (float)
        #pragma unroll
        for (int o = 16; o > 0; o >>= 1) {
            mn = fminf(mn, __shfl_down_sync(0xFFFFFFFFu, mn, o));
            mx = fmaxf(mx, __shfl_down_sync(0xFFFFFFFFu, mx, o));
        }
        __shared__ float wmin[8], wmax[8];
        if (lane == 0) { wmin[w] = mn; wmax[w] = mx; }
        __syncthreads();
        if (w == 0 && lane < 8) {
            mn = wmin[lane];
            mx = wmax[lane];
            #pragma unroll
            for (int o = 4; o > 0; o >>= 1) {
                mn = fminf(mn, __shfl_down_sync(0x000000FFu, mn, o));
                mx = fmaxf(mx, __shfl_down_sync(0x000000FFu, mx, o));
            }
            if (lane == 0) {
                atomicMin(&g_min[s0], f2ord(mn));
                atomicMax(&g_max[s0], f2ord(mx));
            }
        }
        return;
    }

    // ---- slow path: block contains >=1 segment boundary (or grid tail) ----
    __shared__ unsigned int sl_min[P1_SLOTS], sl_max[P1_SLOTS];
    if (t < P1_SLOTS) { sl_min[t] = 0xFFFFFFFFu; sl_max[t] = 0u; }
    __syncthreads();

    int cur_s = -1;
    float cmin = 0.f, cmax = 0.f;
    #pragma unroll
    for (int k = 0; k < 4; ++k) {
        const int idx = base4 + k * 256 + t;
        const int row = idx >> 4;
        if (row < nrows) {
            const int s = __ldg(&seg[row]);
            float4 v = __ldcs(&x4[idx]);
            float vmn = f4min(v), vmx = f4max(v);
            if (s != cur_s) {
                if (cur_s >= 0) {
                    const int slot = cur_s - s0;
                    if (slot < P1_SLOTS) {
                        atomicMin(&sl_min[slot], f2ord(cmin));
                        atomicMax(&sl_max[slot], f2ord(cmax));
                    } else {
                        atomicMin(&g_min[cur_s], f2ord(cmin));
                        atomicMax(&g_max[cur_s], f2ord(cmax));
                    }
                }
                cur_s = s; cmin = vmn; cmax = vmx;
            } else {
                cmin = fminf(cmin, vmn);
                cmax = fmaxf(cmax, vmx);
            }
        }
    }
    if (cur_s >= 0) {
        const int slot = cur_s - s0;
        if (slot < P1_SLOTS) {
            atomicMin(&sl_min[slot], f2ord(cmin));
            atomicMax(&sl_max[slot], f2ord(cmax));
        } else {
            atomicMin(&g_min[cur_s], f2ord(cmin));
            atomicMax(&g_max[cur_s], f2ord(cmax));
        }
    }
    __syncthreads();
    if (t < P1_SLOTS) {
        if (sl_min[t] != 0xFFFFFFFFu) atomicMin(&g_min[s0 + t], sl_min[t]);
        if (sl_max[t] != 0u)          atomicMax(&g_max[s0 + t], sl_max[t]);
    }
}

// Prep: (mn, 1/(mx-mn+eps)) so pass 2 is a subtract + multiply per element.
__global__ void mm_prep() {
    int i = blockIdx.x * blockDim.x + threadIdx.x;
    if (i < NUM_SEG) {
        float mn = ord2f(g_min[i]);
        float mx = ord2f(g_max[i]);
        float inv = 1.0f / (mx - mn + EPS);   // empty segs -> garbage, never read
        g_prm[i] = make_float2(mn, inv);
    }
}

// Pass 2: 4 block-strided float4 per thread, loads front-batched (MLP=4),
// streaming ld/st (touch-once data). g_prm (16 KB) L2-resident; seg hits
// L1 broadcast (16 consecutive threads share one row).
__global__ void __launch_bounds__(256) mm_pass2(const float4* __restrict__ x4,
                                                const int* __restrict__ seg,
                                                float4* __restrict__ o4, int n4) {
    const int stride = blockDim.x;
    const int i0 = blockIdx.x * (stride * 4) + threadIdx.x;

    if (i0 + 3 * stride < n4) {
        float4 v0 = __ldcs(&x4[i0]);
        float4 v1 = __ldcs(&x4[i0 + stride]);
        float4 v2 = __ldcs(&x4[i0 + 2 * stride]);
        float4 v3 = __ldcs(&x4[i0 + 3 * stride]);
        int s0 = __ldg(&seg[i0 >> 4]);
        int s1 = __ldg(&seg[(i0 + stride) >> 4]);
        int s2 = __ldg(&seg[(i0 + 2 * stride) >> 4]);
        int s3 = __ldg(&seg[(i0 + 3 * stride) >> 4]);
        float2 p0 = g_prm[s0], p1 = g_prm[s1], p2 = g_prm[s2], p3 = g_prm[s3];
        float4 r0, r1, r2, r3;
        r0.x=(v0.x-p0.x)*p0.y; r0.y=(v0.y-p0.x)*p0.y; r0.z=(v0.z-p0.x)*p0.y; r0.w=(v0.w-p0.x)*p0.y;
        r1.x=(v1.x-p1.x)*p1.y; r1.y=(v1.y-p1.x)*p1.y; r1.z=(v1.z-p1.x)*p1.y; r1.w=(v1.w-p1.x)*p1.y;
        r2.x=(v2.x-p2.x)*p2.y; r2.y=(v2.y-p2.x)*p2.y; r2.z=(v2.z-p2.x)*p2.y; r2.w=(v2.w-p2.x)*p2.y;
        r3.x=(v3.x-p3.x)*p3.y; r3.y=(v3.y-p3.x)*p3.y; r3.z=(v3.z-p3.x)*p3.y; r3.w=(v3.w-p3.x)*p3.y;
        __stcs(&o4[i0],              r0);
        __stcs(&o4[i0 + stride],     r1);
        __stcs(&o4[i0 + 2 * stride], r2);
        __stcs(&o4[i0 + 3 * stride], r3);
    } else {
        for (int i = i0; i < n4; i += stride) {
            float4 v = __ldcs(&x4[i]);
            int s = __ldg(&seg[i >> 4]);
            float2 p = g_prm[s];
            float4 r;
            r.x=(v.x-p.x)*p.y; r.y=(v.y-p.x)*p.y; r.z=(v.z-p.x)*p.y; r.w=(v.w-p.x)*p.y;
            __stcs(&o4[i], r);
        }
    }
}

extern "C" void kernel_launch(void* const* d_in, const int* in_sizes, int n_in,
                              void* d_out, int out_size) {
    const float* x   = (const float*)d_in[0];
    const int*   seg = (const int*)d_in[1];
    float*       out = (float*)d_out;

    int nrows = in_sizes[1];          // 1,000,000
    int n4    = in_sizes[0] / 4;      // 16,000,000 float4

    // init g_min=UINT_MAX / g_max=0 via byte-fill memsets (graph-capturable)
    void* pmin = nullptr; void* pmax = nullptr;
    cudaGetSymbolAddress(&pmin, g_min);
    cudaGetSymbolAddress(&pmax, g_max);
    cudaMemsetAsync(pmin, 0xFF, NUM_SEG * sizeof(unsigned int), 0);
    cudaMemsetAsync(pmax, 0x00, NUM_SEG * sizeof(unsigned int), 0);

    int blocks1 = (nrows + P1_ROWS - 1) / P1_ROWS;
    mm_pass1<<<blocks1, 256>>>((const float4*)x, seg, nrows);

    mm_prep<<<(NUM_SEG + 255) / 256, 256>>>();

    int blocks2 = (n4 + 1023) / 1024;   // 4 float4 per thread
    mm_pass2<<<blocks2, 256>>>((const float4*)x, seg, (float4*)out, n4);
}